// round 11
// baseline (speedup 1.0000x reference)
#include <cuda_runtime.h>
#include <math.h>
#include <stdint.h>

#define CIN   64
#define COUT  64
#define Hdim  96
#define Wdim  96
#define Bdim  8
#define HW    (Hdim*Wdim)     /* 9216  */
#define PTOT  (Bdim*HW)       /* 73728 */

// Scratch (no cudaMalloc allowed). g_xt padded +64 floats for column-overhang reads.
__device__ float  g_xt [PTOT*CIN + 64];  // NHWC x: [(b*HW+h*96+w)*64 + c]
__device__ float4 g_cf [PTOT*9];         // bilinear coefs (mask folded), [b][k][hw]
__device__ int2   g_bs [PTOT*9];         // clamped row bases (floats offset), [b][k][hw]
__device__ float  g_wtm[9*4096];         // main weights, tf32 fragment-major per tap
__device__ float  g_wo2[9*8*2*32*4];     // offset weights, tf32 fragment-major

// ---------------- helpers --------------------------------------------------
__device__ __forceinline__ void cp_async16(unsigned saddr, const void* g) {
    asm volatile("cp.async.cg.shared.global [%0], [%1], 16;" :: "r"(saddr), "l"(g));
}
__device__ __forceinline__ void cp_commit() { asm volatile("cp.async.commit_group;"); }
__device__ __forceinline__ void cp_wait0()  { asm volatile("cp.async.wait_group 0;"); }

__device__ __forceinline__ uint32_t tf32u(float x) {
    uint32_t r; asm("cvt.rna.tf32.f32 %0, %1;" : "=r"(r) : "f"(x)); return r;
}

// m16n8k8 tf32 MMA
__device__ __forceinline__ void mma_tf32(float4& d, uint32_t a0, uint32_t a1,
                                         uint32_t a2, uint32_t a3,
                                         uint32_t b0, uint32_t b1) {
    asm volatile("mma.sync.aligned.m16n8k8.row.col.f32.tf32.tf32.f32 "
        "{%0,%1,%2,%3}, {%4,%5,%6,%7}, {%8,%9}, {%0,%1,%2,%3};"
        : "+f"(d.x), "+f"(d.y), "+f"(d.z), "+f"(d.w)
        : "r"(a0), "r"(a1), "r"(a2), "r"(a3), "r"(b0), "r"(b1));
}

// ldmatrix x4: A fragment (m16k8 tf32) in one instruction
__device__ __forceinline__ void ldmA(uint32_t& a0, uint32_t& a1,
                                     uint32_t& a2, uint32_t& a3, unsigned addr) {
    asm volatile("ldmatrix.sync.aligned.m8n8.x4.shared.b16 {%0,%1,%2,%3}, [%4];"
        : "=r"(a0), "=r"(a1), "=r"(a2), "=r"(a3) : "r"(addr));
}

// shared meta math: (ys, xs, mask) -> coefs + clamped row bases
__device__ __forceinline__ void make_meta(float ys, float xs, float mk,
                                          float4& cf, int2& bs) {
    float y0f = floorf(ys), x0f = floorf(xs);
    float ty = ys - y0f, tx = xs - x0f;
    int iy0 = (int)y0f, ix0 = (int)x0f;
    float wy0 = (iy0 >= 0 && iy0 <= Hdim-1) ? (1.f - ty) : 0.f;
    float wy1 = (iy0+1 >= 0 && iy0+1 <= Hdim-1) ? ty : 0.f;
    float wx0 = (ix0 >= 0 && ix0 <= Wdim-1) ? (1.f - tx) : 0.f;
    float wx1 = (ix0+1 >= 0 && ix0+1 <= Wdim-1) ? tx : 0.f;
    int bx = min(max(ix0, 0), Wdim-1);
    float cx0 = (ix0 == bx) ? wx0 : ((ix0 + 1 == bx) ? wx1 : 0.f);
    float cx1 = (ix0 == bx) ? wx1 : 0.f;
    int cy0 = min(max(iy0,   0), Hdim-1);
    int cy1 = min(max(iy0+1, 0), Hdim-1);
    cf.x = wy0*cx0*mk;  cf.y = wy0*cx1*mk;
    cf.z = wy1*cx0*mk;  cf.w = wy1*cx1*mk;
    bs = make_int2((cy0*Wdim + bx)*64, (cy1*Wdim + bx)*64);
}

// ---------------------------------------------------------------------------
// Kernel A: NCHW -> NHWC transpose of x
// ---------------------------------------------------------------------------
__global__ __launch_bounds__(256) void dc_transpose(const float* __restrict__ x)
{
    __shared__ float tile[64*65];
    int b  = blockIdx.x / 144;
    int s0 = (blockIdx.x % 144) * 64;
    const float* xb = x + (size_t)b * CIN * HW;
    for (int i = threadIdx.x; i < 64*64; i += 256) {
        int c = i >> 6, s = i & 63;
        tile[c*65 + s] = xb[(size_t)c*HW + s0 + s];
    }
    __syncthreads();
    float* xtb = g_xt + ((size_t)b*HW + s0) * 64;
    for (int i = threadIdx.x; i < 64*64; i += 256) {
        int s = i >> 6, c = i & 63;
        xtb[s*64 + c] = tile[c*65 + s];
    }
    if (blockIdx.x == 0 && threadIdx.x < 64)
        g_xt[(size_t)PTOT*CIN + threadIdx.x] = 0.f;
}

// ---------------------------------------------------------------------------
// Kernel A2: pack weights into tf32 fragment-major layouts.
// ---------------------------------------------------------------------------
__global__ __launch_bounds__(256) void dc_wtrans(const float* __restrict__ w,
                                                 const float* __restrict__ wo)
{
    int i = blockIdx.x * 256 + threadIdx.x;
    if (i < 9*64*64) {
        int o = i / 576, r = i % 576, c = r / 9, k = r % 9;
        int s = c >> 3;
        int lane = (o & 7) * 4 + (c & 3);
        int nt = o >> 3, ntp = nt >> 1;
        int pos = ((nt & 1) << 1) | ((c >> 2) & 1);
        g_wtm[k*4096 + ((s*4 + ntp)*32 + lane)*4 + pos] = __uint_as_float(tf32u(w[i]));
    }
    if (i < 9*8*2*32*4) {
        int pos  = i & 3;
        int lane = (i >> 2) & 31;
        int rest = i >> 7;
        int ntp  = rest & 1;
        int s    = (rest >> 1) & 7;
        int kk   = rest >> 4;
        int m = (2*ntp + (pos >> 1))*8 + (lane >> 2);
        int c = s*8 + (lane & 3) + ((pos & 1) << 2);
        float v = (m < 27) ? wo[(size_t)m*576 + c*9 + kk] : 0.f;
        g_wo2[i] = __uint_as_float(tf32u(v));
    }
}

// ---------------------------------------------------------------------------
// Kernel B: offset conv via mma.sync tf32 -> finished meta (g_cf, g_bs)
// Block = TWO image rows (192 px), 384 threads = 12 warps.
// ---------------------------------------------------------------------------
#define B_SP_SIZE  (4*98*68)                 /* 26656 f */
#define B_SB_OFF   B_SP_SIZE
#define B_SB_SIZE  (9*8*2*32*4)              /* 18432 f */
#define B_OM_OFF   (B_SB_OFF + B_SB_SIZE)
#define B_OM_SIZE  (192*28)
#define B_SMEM_FLOATS (B_OM_OFF + B_OM_SIZE) /* 50464 f = 201.9 KB */

__global__ __launch_bounds__(384, 1) void dc_offsets(const float* __restrict__ b_off)
{
    extern __shared__ float sm[];
    float* sP  = sm;
    float* sB  = sm + B_SB_OFF;
    float* sOm = sm + B_OM_OFF;
    unsigned sbBase = (unsigned)__cvta_generic_to_shared(sB);

    int tid = threadIdx.x;
    int b   = blockIdx.x / (Hdim/2);
    int h0  = (blockIdx.x % (Hdim/2)) * 2;

    for (int i = tid; i < B_SB_SIZE/4; i += 384)
        cp_async16(sbBase + (unsigned)i*16u, g_wo2 + i*4);
    cp_commit();

    const float* xtb = g_xt + (size_t)b * HW * 64;
    for (int r = 0; r < 4; r++) {
        int hh = h0 - 1 + r;
        bool rv = (hh >= 0) & (hh < Hdim);
        for (int i = tid; i < 98*64; i += 384) {
            int col = i >> 6, c = i & 63;
            int ww = col - 1;
            float v = 0.f;
            if (rv && ww >= 0 && ww < Wdim)
                v = xtb[((size_t)hh*Wdim + ww)*64 + c];
            sP[(r*98 + col)*68 + c] = __uint_as_float(tf32u(v));
        }
    }
    cp_wait0();
    __syncthreads();

    int wid  = tid >> 5, lane = tid & 31;
    int g = lane >> 2, t = lane & 3;
    int rp  = wid >> 1;
    int ntp = wid & 1;
    int rowsel = rp / 3;
    int col0   = (rp % 3) * 32;

    float4 d00 = make_float4(0.f,0.f,0.f,0.f);
    float4 d01 = make_float4(0.f,0.f,0.f,0.f);
    float4 d10 = make_float4(0.f,0.f,0.f,0.f);
    float4 d11 = make_float4(0.f,0.f,0.f,0.f);
    const uint32_t* P = (const uint32_t*)sP;

    #pragma unroll
    for (int kk = 0; kk < 9; kk++) {
        int ky = kk / 3, kx = kk % 3;
        const uint32_t* arow0 = P + ((ky + rowsel)*98 + col0 + g + kx)*68;
        const uint32_t* arow1 = arow0 + 16*68;
        #pragma unroll
        for (int s = 0; s < 8; s++) {
            uint32_t a00 = arow0[s*8 + t];
            uint32_t a01 = arow0[8*68 + s*8 + t];
            uint32_t a02 = arow0[s*8 + t + 4];
            uint32_t a03 = arow0[8*68 + s*8 + t + 4];
            uint32_t a10 = arow1[s*8 + t];
            uint32_t a11 = arow1[8*68 + s*8 + t];
            uint32_t a12 = arow1[s*8 + t + 4];
            uint32_t a13 = arow1[8*68 + s*8 + t + 4];
            uint4 bq = *(const uint4*)(sB + (((kk*8 + s)*2 + ntp)*32 + lane)*4);
            mma_tf32(d00, a00,a01,a02,a03, bq.x, bq.y);
            mma_tf32(d01, a00,a01,a02,a03, bq.z, bq.w);
            mma_tf32(d10, a10,a11,a12,a13, bq.x, bq.y);
            mma_tf32(d11, a10,a11,a12,a13, bq.z, bq.w);
        }
    }

    {
        int m0 = 16*ntp + 2*t;
        int m1 = 16*ntp + 8 + 2*t;
        int pxW = rowsel*96 + col0 + g;
        #pragma unroll
        for (int mt = 0; mt < 2; mt++) {
            float4 dv0 = mt ? d10 : d00;
            float4 dv1 = mt ? d11 : d01;
            int pA = pxW + mt*16, pB = pA + 8;
            sOm[pA*28 + m0] = dv0.x + __ldg(&b_off[m0]);
            sOm[pB*28 + m0] = dv0.z + __ldg(&b_off[m0]);
            if (m0 + 1 < 27) {
                sOm[pA*28 + m0+1] = dv0.y + __ldg(&b_off[m0+1]);
                sOm[pB*28 + m0+1] = dv0.w + __ldg(&b_off[m0+1]);
            }
            if (m1 < 27) {
                sOm[pA*28 + m1] = dv1.x + __ldg(&b_off[m1]);
                sOm[pB*28 + m1] = dv1.z + __ldg(&b_off[m1]);
            }
            if (m1 + 1 < 27) {
                sOm[pA*28 + m1+1] = dv1.y + __ldg(&b_off[m1+1]);
                sOm[pB*28 + m1+1] = dv1.w + __ldg(&b_off[m1+1]);
            }
        }
    }
    __syncthreads();

    // transform -> finished meta, coalesced by k-plane
    for (int idx = tid; idx < 192*9; idx += 384) {
        int p2 = idx % 192, k = idx / 192;
        float dy = sOm[p2*28 + 2*k];
        float dx = sOm[p2*28 + 2*k + 1];
        float mv = sOm[p2*28 + 18 + k];
        float mask = 1.0f / (1.0f + __expf(-mv));
        int ky = k / 3, kx = k % 3;
        float ys = (float)(h0 + (p2/96) - 1 + ky) + dy;
        float xs = (float)((p2%96) - 1 + kx) + dx;
        float4 cf; int2 bs;
        make_meta(ys, xs, mask, cf, bs);
        int gi = (b*9 + k)*HW + h0*Wdim + p2;
        g_cf[gi] = cf;
        g_bs[gi] = bs;
    }
}

// ---------------------------------------------------------------------------
// Kernel C: WARP-SPECIALIZED fused sample + mma.sync tf32 GEMM. 2 blocks/SM.
// 256 threads = 8 warps: warps 0-3 = producers (gather 32 px/tap each + B
// cp.async), warps 4-7 = consumers (GEMM 32px x 64o tiles, pure HMMA stream).
// One __syncthreads per tap swaps double buffers.
// smem: sS 2x34816 + sB 2x16384 = 102400 B.
// ---------------------------------------------------------------------------
#define C_SS0    0
#define C_SS1    34816
#define C_SB0    69632
#define C_SB1    86016
#define C_SMEM_BYTES 102400

__global__ __launch_bounds__(256, 2)
void dc_main(const float* __restrict__ bias, float* __restrict__ out)
{
    extern __shared__ char smc[];
    unsigned smem_base = (unsigned)__cvta_generic_to_shared(smc);

    int tid = threadIdx.x;
    int wid = tid >> 5, lane = tid & 31;
    int g = lane >> 2, t = lane & 3;
    int b      = blockIdx.x / 72;
    int pxBase = (blockIdx.x % 72) * 128;
    const float* xtb = g_xt + (size_t)b * HW * 64;
    const float* xtl = xtb + lane*4;

    bool producer = (wid < 4);
    // producer: px range wid*32..+31 per tap
    int pxw = wid * 32;
    // consumer: GEMM tile 32 px x 64 o
    int cw = wid - 4;
    int px0m = cw * 32;

    // ldmatrix lane address components (within sS, stride 68 floats)
    int lp = lane >> 3, lr = lane & 7;
    unsigned aOff0 = (unsigned)(((px0m + ((lp&1)<<3) + lr)*68 + ((lp>>1)<<2)) * 4);
    unsigned aOff1 = aOff0 + 16*68*4;

    float4 acc[16];   // consumer: [mt*8 + nt], o = nt*8, px tile mt
    #pragma unroll
    for (int a = 0; a < 16; a++) acc[a] = make_float4(0.f,0.f,0.f,0.f);

    // producer gather of tap kk into sS buffer at byte offset dstOff
    auto gather_tap = [&](int kk, unsigned dstOff) {
        const float4* cfp = g_cf + (size_t)(b*9 + kk)*HW + pxBase;
        const int2*   bsp = g_bs + (size_t)(b*9 + kk)*HW + pxBase;
        #pragma unroll
        for (int pq = 0; pq < 8; pq++) {
            int2 bs[4]; float4 cf[4]; float4 q0[4], q1[4];
            #pragma unroll
            for (int p = 0; p < 4; p++) {
                int px = pxw + pq*4 + p;
                bs[p] = __ldg(&bsp[px]);
                cf[p] = __ldg(&cfp[px]);
                q0[p] = *(const float4*)(xtl + bs[p].x);
                q1[p] = *(const float4*)(xtl + bs[p].y);
            }
            #pragma unroll
            for (int p = 0; p < 4; p++) {
                float c0 = (lane & 16) ? cf[p].y : cf[p].x;
                float c1 = (lane & 16) ? cf[p].w : cf[p].z;
                float t0 = q0[p].x*c0 + q1[p].x*c1;
                float t1 = q0[p].y*c0 + q1[p].y*c1;
                float t2 = q0[p].z*c0 + q1[p].z*c1;
                float t3 = q0[p].w*c0 + q1[p].w*c1;
                t0 += __shfl_xor_sync(0xffffffffu, t0, 16);
                t1 += __shfl_xor_sync(0xffffffffu, t1, 16);
                t2 += __shfl_xor_sync(0xffffffffu, t2, 16);
                t3 += __shfl_xor_sync(0xffffffffu, t3, 16);
                if (lane < 16) {
                    uint32_t r0 = tf32u(t0), r1 = tf32u(t1),
                             r2 = tf32u(t2), r3 = tf32u(t3);
                    unsigned addr = smem_base + dstOff
                                  + (unsigned)((pxw + pq*4 + p)*68 + lane*4)*4u;
                    asm volatile("st.shared.v4.b32 [%0], {%1, %2, %3, %4};"
                                 :: "r"(addr), "r"(r0), "r"(r1), "r"(r2), "r"(r3));
                }
            }
        }
    };

    // ---- prologue: producers load B(0) + gather tap 0
    if (producer) {
        for (int i = tid; i < 1024; i += 128)
            cp_async16(smem_base + C_SB0 + (unsigned)i*16u, g_wtm + i*4);
        cp_commit();
        gather_tap(0, C_SS0);
        cp_wait0();
    }
    __syncthreads();

    // ---- main loop over taps
    for (int k = 0; k < 9; k++) {
        int cur = k & 1, nxt = cur ^ 1;
        if (producer) {
            if (k < 8) {
                unsigned dstB = smem_base + (nxt ? C_SB1 : C_SB0);
                const float* srcB = g_wtm + (k+1)*4096;
                for (int i = tid; i < 1024; i += 128)
                    cp_async16(dstB + (unsigned)i*16u, srcB + i*4);
                cp_commit();
                gather_tap(k+1, nxt ? C_SS1 : C_SS0);
                cp_wait0();
            }
        } else {
            unsigned ssAddr = smem_base + (cur ? C_SS1 : C_SS0);
            const uint4* sB4 = (const uint4*)(smc + (cur ? C_SB1 : C_SB0));
            #pragma unroll
            for (int s = 0; s < 8; s++) {
                uint32_t a00, a01, a02, a03, a10, a11, a12, a13;
                ldmA(a00, a01, a02, a03, ssAddr + aOff0 + (unsigned)s*32u);
                ldmA(a10, a11, a12, a13, ssAddr + aOff1 + (unsigned)s*32u);
                uint4 bq0 = sB4[(s*4 + 0)*32 + lane];
                uint4 bq1 = sB4[(s*4 + 1)*32 + lane];
                uint4 bq2 = sB4[(s*4 + 2)*32 + lane];
                uint4 bq3 = sB4[(s*4 + 3)*32 + lane];
                mma_tf32(acc[0],  a00,a01,a02,a03, bq0.x, bq0.y);
                mma_tf32(acc[1],  a00,a01,a02,a03, bq0.z, bq0.w);
                mma_tf32(acc[2],  a00,a01,a02,a03, bq1.x, bq1.y);
                mma_tf32(acc[3],  a00,a01,a02,a03, bq1.z, bq1.w);
                mma_tf32(acc[4],  a00,a01,a02,a03, bq2.x, bq2.y);
                mma_tf32(acc[5],  a00,a01,a02,a03, bq2.z, bq2.w);
                mma_tf32(acc[6],  a00,a01,a02,a03, bq3.x, bq3.y);
                mma_tf32(acc[7],  a00,a01,a02,a03, bq3.z, bq3.w);
                mma_tf32(acc[8],  a10,a11,a12,a13, bq0.x, bq0.y);
                mma_tf32(acc[9],  a10,a11,a12,a13, bq0.z, bq0.w);
                mma_tf32(acc[10], a10,a11,a12,a13, bq1.x, bq1.y);
                mma_tf32(acc[11], a10,a11,a12,a13, bq1.z, bq1.w);
                mma_tf32(acc[12], a10,a11,a12,a13, bq2.x, bq2.y);
                mma_tf32(acc[13], a10,a11,a12,a13, bq2.z, bq2.w);
                mma_tf32(acc[14], a10,a11,a12,a13, bq3.x, bq3.y);
                mma_tf32(acc[15], a10,a11,a12,a13, bq3.z, bq3.w);
            }
        }
        __syncthreads();
    }

    // ---- epilogue: consumers write fragments -> sOut[o][px] (stride 132)
    float* sOut = (float*)smc;
    if (!producer) {
        #pragma unroll
        for (int mt = 0; mt < 2; mt++)
            #pragma unroll
            for (int nt = 0; nt < 8; nt++) {
                float4 dv = acc[mt*8 + nt];
                int o = nt*8 + 2*t;
                int pA = px0m + mt*16 + g, pB = pA + 8;
                sOut[o*132 + pA]     = dv.x;
                sOut[(o+1)*132 + pA] = dv.y;
                sOut[o*132 + pB]     = dv.z;
                sOut[(o+1)*132 + pB] = dv.w;
            }
    }
    __syncthreads();
    float* ob = out + (size_t)b * COUT * HW + pxBase;
    for (int i = tid; i < 64*128; i += 256) {
        int o = i >> 7, p = i & 127;
        ob[(size_t)o*HW + p] = sOut[o*132 + p] + __ldg(&bias[o]);
    }
}

// ---------------------------------------------------------------------------
extern "C" void kernel_launch(void* const* d_in, const int* in_sizes, int n_in,
                              void* d_out, int out_size)
{
    const float* x      = (const float*)d_in[0];
    const float* w_off  = (const float*)d_in[1];
    const float* b_off  = (const float*)d_in[2];
    const float* weight = (const float*)d_in[3];
    const float* bias   = (const float*)d_in[4];
    float* out = (float*)d_out;

    static bool attr_done = false;
    if (!attr_done) {
        cudaFuncSetAttribute(dc_offsets, cudaFuncAttributeMaxDynamicSharedMemorySize,
                             B_SMEM_FLOATS * (int)sizeof(float));
        cudaFuncSetAttribute(dc_main, cudaFuncAttributeMaxDynamicSharedMemorySize,
                             C_SMEM_BYTES);
        attr_done = true;
    }

    dc_transpose<<<Bdim * (HW/64), 256>>>(x);
    dc_wtrans   <<<(9*64*64 + 255)/256, 256>>>(weight, w_off);
    dc_offsets  <<<Bdim * (Hdim/2), 384, B_SMEM_FLOATS * sizeof(float)>>>(b_off);
    dc_main     <<<Bdim * 72, 256, C_SMEM_BYTES>>>(bias, out);
}

// round 12
// speedup vs baseline: 1.4592x; 1.4592x over previous
#include <cuda_runtime.h>
#include <cuda_fp16.h>
#include <math.h>
#include <stdint.h>

#define CIN   64
#define COUT  64
#define Hdim  96
#define Wdim  96
#define Bdim  8
#define HW    (Hdim*Wdim)     /* 9216  */
#define PTOT  (Bdim*HW)       /* 73728 */

// Scratch (no cudaMalloc allowed).
__device__ __half g_xt [PTOT*CIN + 128]; // NHWC x fp16: [(b*HW+h*96+w)*64 + c]
__device__ uint2  g_cfh[PTOT*9];         // packed half coefs {c00,c01},{c10,c11}
__device__ int2   g_bs [PTOT*9];         // clamped row bases (half-element offset)
__device__ uint4  g_wtmh[9*16*32];       // main weights fp16 fragment-major per tap
__device__ float  g_wo2[9*8*2*32*4];     // offset weights, tf32 fragment-major

// ---------------- helpers --------------------------------------------------
__device__ __forceinline__ void cp_async16(unsigned saddr, const void* g) {
    asm volatile("cp.async.cg.shared.global [%0], [%1], 16;" :: "r"(saddr), "l"(g));
}
__device__ __forceinline__ void cp_commit() { asm volatile("cp.async.commit_group;"); }
__device__ __forceinline__ void cp_wait0()  { asm volatile("cp.async.wait_group 0;"); }

__device__ __forceinline__ uint32_t tf32u(float x) {
    uint32_t r; asm("cvt.rna.tf32.f32 %0, %1;" : "=r"(r) : "f"(x)); return r;
}

// m16n8k8 tf32 MMA (offset conv)
__device__ __forceinline__ void mma_tf32(float4& d, uint32_t a0, uint32_t a1,
                                         uint32_t a2, uint32_t a3,
                                         uint32_t b0, uint32_t b1) {
    asm volatile("mma.sync.aligned.m16n8k8.row.col.f32.tf32.tf32.f32 "
        "{%0,%1,%2,%3}, {%4,%5,%6,%7}, {%8,%9}, {%0,%1,%2,%3};"
        : "+f"(d.x), "+f"(d.y), "+f"(d.z), "+f"(d.w)
        : "r"(a0), "r"(a1), "r"(a2), "r"(a3), "r"(b0), "r"(b1));
}

// m16n8k16 fp16 MMA, fp32 accum (main conv)
__device__ __forceinline__ void mma_f16(float4& d, uint32_t a0, uint32_t a1,
                                        uint32_t a2, uint32_t a3,
                                        uint32_t b0, uint32_t b1) {
    asm volatile("mma.sync.aligned.m16n8k16.row.col.f32.f16.f16.f32 "
        "{%0,%1,%2,%3}, {%4,%5,%6,%7}, {%8,%9}, {%0,%1,%2,%3};"
        : "+f"(d.x), "+f"(d.y), "+f"(d.z), "+f"(d.w)
        : "r"(a0), "r"(a1), "r"(a2), "r"(a3), "r"(b0), "r"(b1));
}

__device__ __forceinline__ void ldmA(uint32_t& a0, uint32_t& a1,
                                     uint32_t& a2, uint32_t& a3, unsigned addr) {
    asm volatile("ldmatrix.sync.aligned.m8n8.x4.shared.b16 {%0,%1,%2,%3}, [%4];"
        : "=r"(a0), "=r"(a1), "=r"(a2), "=r"(a3) : "r"(addr));
}

// meta math: (ys, xs, mask) -> coefs + clamped row bases (half-element units)
__device__ __forceinline__ void make_meta(float ys, float xs, float mk,
                                          float4& cf, int2& bs) {
    float y0f = floorf(ys), x0f = floorf(xs);
    float ty = ys - y0f, tx = xs - x0f;
    int iy0 = (int)y0f, ix0 = (int)x0f;
    float wy0 = (iy0 >= 0 && iy0 <= Hdim-1) ? (1.f - ty) : 0.f;
    float wy1 = (iy0+1 >= 0 && iy0+1 <= Hdim-1) ? ty : 0.f;
    float wx0 = (ix0 >= 0 && ix0 <= Wdim-1) ? (1.f - tx) : 0.f;
    float wx1 = (ix0+1 >= 0 && ix0+1 <= Wdim-1) ? tx : 0.f;
    int bx = min(max(ix0, 0), Wdim-1);
    float cx0 = (ix0 == bx) ? wx0 : ((ix0 + 1 == bx) ? wx1 : 0.f);
    float cx1 = (ix0 == bx) ? wx1 : 0.f;
    int cy0 = min(max(iy0,   0), Hdim-1);
    int cy1 = min(max(iy0+1, 0), Hdim-1);
    cf.x = wy0*cx0*mk;  cf.y = wy0*cx1*mk;
    cf.z = wy1*cx0*mk;  cf.w = wy1*cx1*mk;
    bs = make_int2((cy0*Wdim + bx)*64, (cy1*Wdim + bx)*64);
}

// ---------------------------------------------------------------------------
// Kernel A: NCHW fp32 -> NHWC fp16
// ---------------------------------------------------------------------------
__global__ __launch_bounds__(256) void dc_transpose(const float* __restrict__ x)
{
    __shared__ float tile[64*65];
    int b  = blockIdx.x / 144;
    int s0 = (blockIdx.x % 144) * 64;
    const float* xb = x + (size_t)b * CIN * HW;
    for (int i = threadIdx.x; i < 64*64; i += 256) {
        int c = i >> 6, s = i & 63;
        tile[c*65 + s] = xb[(size_t)c*HW + s0 + s];
    }
    __syncthreads();
    __half* xtb = g_xt + ((size_t)b*HW + s0) * 64;
    for (int i = threadIdx.x; i < 64*64; i += 256) {
        int s = i >> 6, c = i & 63;
        xtb[s*64 + c] = __float2half(tile[c*65 + s]);
    }
    if (blockIdx.x == 0 && threadIdx.x < 128)
        g_xt[(size_t)PTOT*CIN + threadIdx.x] = __float2half(0.f);
}

// ---------------------------------------------------------------------------
// Kernel A2: pack weights.
// Main fp16 frag-major: per tap k, kstep s(K=16), ntp(0..3), lane: uint4 =
//  {b0(nt0),b1(nt0),b0(nt1),b1(nt1)}, nt0=2ntp, nt1=2ntp+1;
//  b0 halves: c = s*16+(lane&3)*2+{0,1}, o = nt*8+(lane>>2); b1: c += 8.
// ---------------------------------------------------------------------------
__global__ __launch_bounds__(256) void dc_wtrans(const float* __restrict__ w,
                                                 const float* __restrict__ wo)
{
    int i = blockIdx.x * 256 + threadIdx.x;
    if (i < 9*16*32) {
        int k = i / 512, q = i % 512;
        int lane = q & 31, sp = q >> 5;
        int s = sp >> 2, ntp = sp & 3;
        unsigned short hs[8];
        #pragma unroll
        for (int j = 0; j < 8; j++) {
            int nt = 2*ntp + (j >> 2);
            int creg = (j >> 1) & 1;
            int c = s*16 + (lane & 3)*2 + (j & 1) + creg*8;
            int o = nt*8 + (lane >> 2);
            __half h = __float2half(w[(size_t)o*576 + c*9 + k]);
            hs[j] = *(unsigned short*)&h;
        }
        uint4 v;
        v.x = (uint32_t)hs[0] | ((uint32_t)hs[1] << 16);
        v.y = (uint32_t)hs[2] | ((uint32_t)hs[3] << 16);
        v.z = (uint32_t)hs[4] | ((uint32_t)hs[5] << 16);
        v.w = (uint32_t)hs[6] | ((uint32_t)hs[7] << 16);
        g_wtmh[i] = v;
    }
    if (i < 9*8*2*32*4) {
        int pos  = i & 3;
        int lane = (i >> 2) & 31;
        int rest = i >> 7;
        int ntp  = rest & 1;
        int s    = (rest >> 1) & 7;
        int kk   = rest >> 4;
        int m = (2*ntp + (pos >> 1))*8 + (lane >> 2);
        int c = s*8 + (lane & 3) + ((pos & 1) << 2);
        float v = (m < 27) ? wo[(size_t)m*576 + c*9 + kk] : 0.f;
        g_wo2[i] = __uint_as_float(tf32u(v));
    }
}

// ---------------------------------------------------------------------------
// Kernel B: offset conv via mma.sync tf32 -> finished packed meta
// Block = TWO image rows (192 px), 384 threads = 12 warps.
// ---------------------------------------------------------------------------
#define B_SP_SIZE  (4*98*68)
#define B_SB_OFF   B_SP_SIZE
#define B_SB_SIZE  (9*8*2*32*4)
#define B_OM_OFF   (B_SB_OFF + B_SB_SIZE)
#define B_OM_SIZE  (192*28)
#define B_SMEM_FLOATS (B_OM_OFF + B_OM_SIZE)

__global__ __launch_bounds__(384, 1) void dc_offsets(const float* __restrict__ b_off)
{
    extern __shared__ float sm[];
    float* sP  = sm;
    float* sB  = sm + B_SB_OFF;
    float* sOm = sm + B_OM_OFF;
    unsigned sbBase = (unsigned)__cvta_generic_to_shared(sB);

    int tid = threadIdx.x;
    int b   = blockIdx.x / (Hdim/2);
    int h0  = (blockIdx.x % (Hdim/2)) * 2;

    for (int i = tid; i < B_SB_SIZE/4; i += 384)
        cp_async16(sbBase + (unsigned)i*16u, g_wo2 + i*4);
    cp_commit();

    const __half* xtb = g_xt + (size_t)b * HW * 64;
    for (int r = 0; r < 4; r++) {
        int hh = h0 - 1 + r;
        bool rv = (hh >= 0) & (hh < Hdim);
        for (int i = tid; i < 98*64; i += 384) {
            int col = i >> 6, c = i & 63;
            int ww = col - 1;
            float v = 0.f;
            if (rv && ww >= 0 && ww < Wdim)
                v = __half2float(xtb[((size_t)hh*Wdim + ww)*64 + c]);
            sP[(r*98 + col)*68 + c] = __uint_as_float(tf32u(v));
        }
    }
    cp_wait0();
    __syncthreads();

    int wid  = tid >> 5, lane = tid & 31;
    int g = lane >> 2, t = lane & 3;
    int rp  = wid >> 1;
    int ntp = wid & 1;
    int rowsel = rp / 3;
    int col0   = (rp % 3) * 32;

    float4 d00 = make_float4(0.f,0.f,0.f,0.f);
    float4 d01 = make_float4(0.f,0.f,0.f,0.f);
    float4 d10 = make_float4(0.f,0.f,0.f,0.f);
    float4 d11 = make_float4(0.f,0.f,0.f,0.f);
    const uint32_t* P = (const uint32_t*)sP;

    #pragma unroll
    for (int kk = 0; kk < 9; kk++) {
        int ky = kk / 3, kx = kk % 3;
        const uint32_t* arow0 = P + ((ky + rowsel)*98 + col0 + g + kx)*68;
        const uint32_t* arow1 = arow0 + 16*68;
        #pragma unroll
        for (int s = 0; s < 8; s++) {
            uint32_t a00 = arow0[s*8 + t];
            uint32_t a01 = arow0[8*68 + s*8 + t];
            uint32_t a02 = arow0[s*8 + t + 4];
            uint32_t a03 = arow0[8*68 + s*8 + t + 4];
            uint32_t a10 = arow1[s*8 + t];
            uint32_t a11 = arow1[8*68 + s*8 + t];
            uint32_t a12 = arow1[s*8 + t + 4];
            uint32_t a13 = arow1[8*68 + s*8 + t + 4];
            uint4 bq = *(const uint4*)(sB + (((kk*8 + s)*2 + ntp)*32 + lane)*4);
            mma_tf32(d00, a00,a01,a02,a03, bq.x, bq.y);
            mma_tf32(d01, a00,a01,a02,a03, bq.z, bq.w);
            mma_tf32(d10, a10,a11,a12,a13, bq.x, bq.y);
            mma_tf32(d11, a10,a11,a12,a13, bq.z, bq.w);
        }
    }

    {
        int m0 = 16*ntp + 2*t;
        int m1 = 16*ntp + 8 + 2*t;
        int pxW = rowsel*96 + col0 + g;
        #pragma unroll
        for (int mt = 0; mt < 2; mt++) {
            float4 dv0 = mt ? d10 : d00;
            float4 dv1 = mt ? d11 : d01;
            int pA = pxW + mt*16, pB = pA + 8;
            sOm[pA*28 + m0] = dv0.x + __ldg(&b_off[m0]);
            sOm[pB*28 + m0] = dv0.z + __ldg(&b_off[m0]);
            if (m0 + 1 < 27) {
                sOm[pA*28 + m0+1] = dv0.y + __ldg(&b_off[m0+1]);
                sOm[pB*28 + m0+1] = dv0.w + __ldg(&b_off[m0+1]);
            }
            if (m1 < 27) {
                sOm[pA*28 + m1] = dv1.x + __ldg(&b_off[m1]);
                sOm[pB*28 + m1] = dv1.z + __ldg(&b_off[m1]);
            }
            if (m1 + 1 < 27) {
                sOm[pA*28 + m1+1] = dv1.y + __ldg(&b_off[m1+1]);
                sOm[pB*28 + m1+1] = dv1.w + __ldg(&b_off[m1+1]);
            }
        }
    }
    __syncthreads();

    for (int idx = tid; idx < 192*9; idx += 384) {
        int p2 = idx % 192, k = idx / 192;
        float dy = sOm[p2*28 + 2*k];
        float dx = sOm[p2*28 + 2*k + 1];
        float mv = sOm[p2*28 + 18 + k];
        float mask = 1.0f / (1.0f + __expf(-mv));
        int ky = k / 3, kx = k % 3;
        float ys = (float)(h0 + (p2/96) - 1 + ky) + dy;
        float xs = (float)((p2%96) - 1 + kx) + dx;
        float4 cf; int2 bs;
        make_meta(ys, xs, mask, cf, bs);
        int gi = (b*9 + k)*HW + h0*Wdim + p2;
        __half2 h01 = __floats2half2_rn(cf.x, cf.y);
        __half2 h23 = __floats2half2_rn(cf.z, cf.w);
        uint2 u;
        u.x = *(uint32_t*)&h01;
        u.y = *(uint32_t*)&h23;
        g_cfh[gi] = u;
        g_bs[gi]  = bs;
    }
}

// ---------------------------------------------------------------------------
// Kernel C: fused fp16 bilinear sample + mma.sync m16n8k16 GEMM. 2 blocks/SM.
// Block = 128 px, 256 threads = 8 warps (all warps gather + GEMM, round-8
// interleave). Gather: 2 px per iteration, one LDG.128 per row covers both px.
// A tile fp16 smem row stride 72 halves (144 B); B tile fp16 8 KB/tap.
// smem: sS 2x18432 + sB 2x8192 = 53248 B.
// ---------------------------------------------------------------------------
#define C_SS0    0
#define C_SS1    18432
#define C_SB0    36864
#define C_SB1    45056
#define C_SMEM_BYTES 53248

__global__ __launch_bounds__(256, 2)
void dc_main(const float* __restrict__ bias, float* __restrict__ out)
{
    extern __shared__ char smc[];
    unsigned smem_base = (unsigned)__cvta_generic_to_shared(smc);

    int tid = threadIdx.x;
    int wid = tid >> 5, lane = tid & 31;
    int g = lane >> 2, t = lane & 3;
    int b      = blockIdx.x / 72;
    int pxBase = (blockIdx.x % 72) * 128;
    const __half* xh = g_xt + (size_t)b * HW * 64;
    int warpPx0 = wid * 16;          // gather: 16 px per warp
    int mq = wid & 3, oh = wid >> 2; // GEMM: 32 px x 32 o tile
    int px0m = mq * 32;

    // gather lane roles
    int gsel = lane >> 4;            // which px of the pair
    int gcol = (lane >> 3) & 1;      // bilinear column
    int goct = lane & 7;             // channel octet (8 fp16)

    // ldmatrix lane address (A tile stride 144 B)
    int rowl = (lane & 7) + (((lane >> 3) & 1) << 3);
    unsigned aOff0 = (unsigned)((px0m + rowl) * 144 + ((lane >> 4) << 4));
    unsigned aOff1 = aOff0 + 16u*144u;

    float4 acc[8];   // [mt*4 + nt], o = oh*32 + nt*8
    #pragma unroll
    for (int a = 0; a < 8; a++) acc[a] = make_float4(0.f,0.f,0.f,0.f);

    const uint4* Bg = g_wtmh;

    // ---- gather one 2-px pair of tap kk into buffer dstOff
    auto gather_pair = [&](const int2* bsp, const uint2* cfp, int p0, unsigned dstOff) {
        int myPx = p0 + gsel;
        int2  bs = __ldg(&bsp[myPx]);
        uint2 cf = __ldg(&cfp[myPx]);
        const __half* r0 = xh + bs.x + gcol*64 + goct*8;
        const __half* r1 = xh + bs.y + gcol*64 + goct*8;
        uint4 qA = *(const uint4*)r0;
        uint4 qB = *(const uint4*)r1;
        __half2 cfx = *(__half2*)&cf.x;
        __half2 cfy = *(__half2*)&cf.y;
        __half2 cA = __half2half2(gcol ? __high2half(cfx) : __low2half(cfx));
        __half2 cB = __half2half2(gcol ? __high2half(cfy) : __low2half(cfy));
        __half2 v0 = __hfma2(*(__half2*)&qB.x, cB, __hmul2(*(__half2*)&qA.x, cA));
        __half2 v1 = __hfma2(*(__half2*)&qB.y, cB, __hmul2(*(__half2*)&qA.y, cA));
        __half2 v2 = __hfma2(*(__half2*)&qB.z, cB, __hmul2(*(__half2*)&qA.z, cA));
        __half2 v3 = __hfma2(*(__half2*)&qB.w, cB, __hmul2(*(__half2*)&qA.w, cA));
        uint32_t u0 = __shfl_xor_sync(0xffffffffu, *(uint32_t*)&v0, 8);
        uint32_t u1 = __shfl_xor_sync(0xffffffffu, *(uint32_t*)&v1, 8);
        uint32_t u2 = __shfl_xor_sync(0xffffffffu, *(uint32_t*)&v2, 8);
        uint32_t u3 = __shfl_xor_sync(0xffffffffu, *(uint32_t*)&v3, 8);
        __half2 w0 = __hadd2(v0, *(__half2*)&u0);
        __half2 w1 = __hadd2(v1, *(__half2*)&u1);
        __half2 w2 = __hadd2(v2, *(__half2*)&u2);
        __half2 w3 = __hadd2(v3, *(__half2*)&u3);
        if ((lane & 8) == 0) {
            unsigned addr = smem_base + dstOff + (unsigned)(myPx*144 + goct*16);
            asm volatile("st.shared.v4.b32 [%0], {%1, %2, %3, %4};"
                :: "r"(addr), "r"(*(uint32_t*)&w0), "r"(*(uint32_t*)&w1),
                   "r"(*(uint32_t*)&w2), "r"(*(uint32_t*)&w3));
        }
    };

    // ---- prologue: B(0) cp.async; gather(0)
    for (int i = tid; i < 512; i += 256)
        cp_async16(smem_base + C_SB0 + (unsigned)i*16u, Bg + i);
    cp_commit();
    {
        const int2*  bsp = g_bs  + (size_t)(b*9 + 0)*HW + pxBase;
        const uint2* cfp = g_cfh + (size_t)(b*9 + 0)*HW + pxBase;
        #pragma unroll
        for (int pq = 0; pq < 8; pq++)
            gather_pair(bsp, cfp, warpPx0 + pq*2, C_SS0);
    }
    cp_wait0();
    __syncthreads();

    // ---- main loop over taps
    for (int k = 0; k < 9; k++) {
        int cur = k & 1, nxt = cur ^ 1;
        if (k < 8) {
            unsigned dstB = smem_base + (nxt ? C_SB1 : C_SB0);
            const uint4* srcB = Bg + (size_t)(k+1)*512;
            for (int i = tid; i < 512; i += 256)
                cp_async16(dstB + (unsigned)i*16u, srcB + i);
            cp_commit();
        }
        unsigned ssAddr = smem_base + (cur ? C_SS1 : C_SS0);
        const uint4* sB4 = (const uint4*)(smc + (cur ? C_SB1 : C_SB0));
        unsigned gdst = (unsigned)(nxt ? C_SS1 : C_SS0);
        int kn = (k+1 < 9) ? k+1 : 0;
        const int2*  bsp = g_bs  + (size_t)(b*9 + kn)*HW + pxBase;
        const uint2* cfp = g_cfh + (size_t)(b*9 + kn)*HW + pxBase;

        #pragma unroll
        for (int ch = 0; ch < 4; ch++) {
            // gather(k+1): 2 pair-iterations (4 px)
            if (k < 8) {
                gather_pair(bsp, cfp, warpPx0 + ch*4,     gdst);
                gather_pair(bsp, cfp, warpPx0 + ch*4 + 2, gdst);
            }
            // GEMM kstep s = ch (K=16)
            {
                uint32_t a00, a01, a02, a03, a10, a11, a12, a13;
                ldmA(a00, a01, a02, a03, ssAddr + aOff0 + (unsigned)ch*32u);
                ldmA(a10, a11, a12, a13, ssAddr + aOff1 + (unsigned)ch*32u);
                uint4 bq0 = sB4[(ch*4 + 2*oh    )*32 + lane];
                uint4 bq1 = sB4[(ch*4 + 2*oh + 1)*32 + lane];
                mma_f16(acc[0], a00,a01,a02,a03, bq0.x, bq0.y);
                mma_f16(acc[1], a00,a01,a02,a03, bq0.z, bq0.w);
                mma_f16(acc[2], a00,a01,a02,a03, bq1.x, bq1.y);
                mma_f16(acc[3], a00,a01,a02,a03, bq1.z, bq1.w);
                mma_f16(acc[4], a10,a11,a12,a13, bq0.x, bq0.y);
                mma_f16(acc[5], a10,a11,a12,a13, bq0.z, bq0.w);
                mma_f16(acc[6], a10,a11,a12,a13, bq1.x, bq1.y);
                mma_f16(acc[7], a10,a11,a12,a13, bq1.z, bq1.w);
            }
        }
        cp_wait0();
        __syncthreads();
    }

    // ---- epilogue: fragments -> sOut[o][px] (stride 132), then NCHW store
    float* sOut = (float*)smc;
    #pragma unroll
    for (int mt = 0; mt < 2; mt++)
        #pragma unroll
        for (int nt = 0; nt < 4; nt++) {
            float4 dv = acc[mt*4 + nt];
            int o = oh*32 + nt*8 + 2*t;
            int pA = px0m + mt*16 + g, pB = pA + 8;
            sOut[o*132 + pA]     = dv.x;
            sOut[(o+1)*132 + pA] = dv.y;
            sOut[o*132 + pB]     = dv.z;
            sOut[(o+1)*132 + pB] = dv.w;
        }
    __syncthreads();
    float* ob = out + (size_t)b * COUT * HW + pxBase;
    for (int i = tid; i < 64*128; i += 256) {
        int o = i >> 7, p = i & 127;
        ob[(size_t)o*HW + p] = sOut[o*132 + p] + __ldg(&bias[o]);
    }
}

// ---------------------------------------------------------------------------
extern "C" void kernel_launch(void* const* d_in, const int* in_sizes, int n_in,
                              void* d_out, int out_size)
{
    const float* x      = (const float*)d_in[0];
    const float* w_off  = (const float*)d_in[1];
    const float* b_off  = (const float*)d_in[2];
    const float* weight = (const float*)d_in[3];
    const float* bias   = (const float*)d_in[4];
    float* out = (float*)d_out;

    static bool attr_done = false;
    if (!attr_done) {
        cudaFuncSetAttribute(dc_offsets, cudaFuncAttributeMaxDynamicSharedMemorySize,
                             B_SMEM_FLOATS * (int)sizeof(float));
        cudaFuncSetAttribute(dc_main, cudaFuncAttributeMaxDynamicSharedMemorySize,
                             C_SMEM_BYTES);
        attr_done = true;
    }

    dc_transpose<<<Bdim * (HW/64), 256>>>(x);
    dc_wtrans   <<<(9*64*64 + 255)/256, 256>>>(weight, w_off);
    dc_offsets  <<<Bdim * (Hdim/2), 384, B_SMEM_FLOATS * sizeof(float)>>>(b_off);
    dc_main     <<<Bdim * 72, 256, C_SMEM_BYTES>>>(bias, out);
}